// round 14
// baseline (speedup 1.0000x reference)
#include <cuda_runtime.h>
#include <cuda_fp16.h>
#include <math.h>
#include <cstdint>

#define NN   16384
#define DD   16
#define FIN  512
#define FOUT 512
#define RR   8
#define HIDD 64
#define BN_EPS 1e-5f
#define RESIDUAL 0.12f

// ---------------- scratch (device globals: allocation-free), per-pass ----------------
__device__ __half g_att  [2ull * NN * RR * FIN];    // 268 MB (fp16)
__device__ __half g_srcz [2ull * NN * RR * FOUT];   // 268 MB (fp16)
__device__ __half g_hz   [2ull * NN * FOUT];        // 33 MB (fp16)
__device__ __half g_wt   [2ull * FIN * FOUT];       // 1 MB
__device__ __half g_hconv[2ull * NN * FIN];         // 34 MB

__device__ __forceinline__ float lrelu(float x) { return x >= 0.0f ? x : 0.2f * x; }

__device__ __forceinline__ uint32_t smem_u32(const void* p) {
    uint32_t a;
    asm("{ .reg .u64 t; cvta.to.shared.u64 t, %1; cvt.u32.u64 %0, t; }" : "=r"(a) : "l"(p));
    return a;
}
__device__ __forceinline__ void cp_async16(uint32_t dst, const void* src) {
    asm volatile("cp.async.cg.shared.global [%0], [%1], 16;" :: "r"(dst), "l"(src));
}
#define CP_COMMIT() asm volatile("cp.async.commit_group;" ::: "memory")
#define CP_WAIT(n)  asm volatile("cp.async.wait_group %0;" :: "n"(n) : "memory")

__device__ __forceinline__ void ldsm_x4(uint32_t* r, uint32_t addr) {
    asm volatile("ldmatrix.sync.aligned.m8n8.x4.shared.b16 {%0,%1,%2,%3}, [%4];"
        : "=r"(r[0]), "=r"(r[1]), "=r"(r[2]), "=r"(r[3]) : "r"(addr));
}

__device__ __forceinline__ void mma_f16(float& c0, float& c1, float& c2, float& c3,
                                        uint32_t a0, uint32_t a1, uint32_t a2, uint32_t a3,
                                        uint32_t b0, uint32_t b1) {
    asm volatile(
        "mma.sync.aligned.m16n8k16.row.col.f32.f16.f16.f32 "
        "{%0,%1,%2,%3}, {%4,%5,%6,%7}, {%8,%9}, {%0,%1,%2,%3};"
        : "+f"(c0), "+f"(c1), "+f"(c2), "+f"(c3)
        : "r"(a0), "r"(a1), "r"(a2), "r"(a3), "r"(b0), "r"(b1));
}

// ---------------- kernel 0a: transpose W [K,N] -> WT [N,K], fp16 (both passes) --------
__global__ void transposeW_kernel(const float* __restrict__ W0,
                                  const float* __restrict__ W1,
                                  __half* __restrict__ WT)
{
    int pass = blockIdx.z;
    const float* W = pass ? W1 : W0;
    __half* wt = WT + (size_t)pass * FIN * FOUT;
    __shared__ float t[32][33];
    int bx = blockIdx.x * 32, by = blockIdx.y * 32;
    t[threadIdx.y][threadIdx.x] = W[(by + threadIdx.y) * FOUT + bx + threadIdx.x];
    __syncthreads();
    wt[(bx + threadIdx.y) * FIN + by + threadIdx.x] = __float2half_rn(t[threadIdx.x][threadIdx.y]);
}

// ---------------- kernel 0b: convert h to fp16 (both passes) ----------------
__global__ void convert_kernel(const float* __restrict__ h0,
                               const float* __restrict__ h1,
                               __half* __restrict__ out, int n4)
{
    int pass = blockIdx.y;
    const float* in = pass ? h1 : h0;
    __half* o = out + (size_t)pass * NN * FIN;
    int i = blockIdx.x * blockDim.x + threadIdx.x;
    if (i < n4) {
        float4 v = reinterpret_cast<const float4*>(in)[i];
        __half2 hh0 = __floats2half2_rn(v.x, v.y);
        __half2 hh1 = __floats2half2_rn(v.z, v.w);
        uint2 st;
        st.x = *reinterpret_cast<uint32_t*>(&hh0);
        st.y = *reinterpret_cast<uint32_t*>(&hh1);
        reinterpret_cast<uint2*>(o)[i] = st;
    }
}

// ---------------- kernel 1: relation maxpool via counting sort ----------------
__global__ void maxpool_kernel(const float* __restrict__ src0,
                               const float* __restrict__ src1,
                               const int*   __restrict__ rel,
                               __half*      __restrict__ attBase)
{
    int n    = blockIdx.x;
    int pass = blockIdx.y;
    const float* src = pass ? src1 : src0;
    __half* att = attBase + (size_t)pass * NN * RR * FIN;
    int tid = threadIdx.x;  // 128

    __shared__ int cnt[RR];
    __shared__ int ord[DD];
    __shared__ int relIdx[DD];
    __shared__ int isLast[DD];
    __shared__ int rl[DD];

    if (tid < RR) cnt[tid] = 0;
    __syncthreads();
    if (tid < DD) {
        int r = rel[n * DD + tid];
        rl[tid] = r;
        atomicAdd(&cnt[r], 1);
    }
    __syncthreads();
    if (tid == 0) {
        int pos[RR];
        int s = 0;
#pragma unroll
        for (int r = 0; r < RR; r++) { pos[r] = s; s += cnt[r]; }
#pragma unroll
        for (int d = 0; d < DD; d++) {
            int r = rl[d];
            int p = pos[r]++;
            ord[p] = d;
            relIdx[p] = r;
        }
#pragma unroll
        for (int i = 0; i < DD - 1; i++) isLast[i] = (relIdx[i + 1] != relIdx[i]);
        isLast[DD - 1] = 1;
    }
    __syncthreads();

    const float4* sp = reinterpret_cast<const float4*>(src + (size_t)n * DD * FIN);
    uint2* ap = reinterpret_cast<uint2*>(att + (size_t)n * RR * FIN);

    uint2 zz; zz.x = 0u; zz.y = 0u;
#pragma unroll
    for (int r = 0; r < RR; r++)
        if (cnt[r] == 0) ap[r * (FIN / 4) + tid] = zz;

    const float NEG = -3.402823466e38f;
    float4 acc = make_float4(NEG, NEG, NEG, NEG);

#pragma unroll
    for (int i = 0; i < DD; i++) {
        float4 v = sp[ord[i] * (FIN / 4) + tid];
        acc.x = fmaxf(acc.x, v.x);
        acc.y = fmaxf(acc.y, v.y);
        acc.z = fmaxf(acc.z, v.z);
        acc.w = fmaxf(acc.w, v.w);
        if (isLast[i]) {
            int r = relIdx[i];
            float4 o = acc;
            if (cnt[r] != DD) {
                o.x = fmaxf(o.x, 0.0f);
                o.y = fmaxf(o.y, 0.0f);
                o.z = fmaxf(o.z, 0.0f);
                o.w = fmaxf(o.w, 0.0f);
            }
            __half2 h0 = __floats2half2_rn(o.x, o.y);
            __half2 h1 = __floats2half2_rn(o.z, o.w);
            uint2 st;
            st.x = *reinterpret_cast<uint32_t*>(&h0);
            st.y = *reinterpret_cast<uint32_t*>(&h1);
            ap[r * (FIN / 4) + tid] = st;
            acc = make_float4(NEG, NEG, NEG, NEG);
        }
    }
}

// ---------------- kernel 2: mma.sync fp16 GEMM (both passes via z) -------
#define TSH 72
#define STAGE_HALFS ((128 + 128) * TSH)
#define GSTAGES 3
#define GEMM_SMEM (GSTAGES * STAGE_HALFS * 2)    // 110592 bytes
#define MBBIG (NN * RR / 128)

__global__ void __launch_bounds__(256, 2)
gemm_tc_kernel(const __half* __restrict__ attB,
               const __half* __restrict__ hconvB,
               const __half* __restrict__ wtB,
               __half*       __restrict__ srczB,
               __half*       __restrict__ hzB)
{
    extern __shared__ __half smh[];
    int tid  = threadIdx.x;
    int wid  = tid >> 5;
    int lane = tid & 31;
    int wm   = wid & 1;
    int wn   = wid >> 1;
    int g    = lane >> 2;
    int t    = lane & 3;
    int q    = lane >> 3;
    int lr   = lane & 7;

    int pass = blockIdx.z;
    const __half* Bt = wtB + (size_t)pass * FIN * FOUT;

    int mb = blockIdx.y;
    const __half* A;
    __half* C;
    int bm;
    if (mb < MBBIG) {
        A = attB  + (size_t)pass * NN * RR * FIN;
        C = srczB + (size_t)pass * NN * RR * FOUT;
        bm = mb * 128;
    } else {
        A = hconvB + (size_t)pass * NN * FIN;
        C = hzB    + (size_t)pass * NN * FOUT;
        bm = (mb - MBBIG) * 128;
    }
    int bn = blockIdx.x * 128;

    int row0 = tid >> 3;
    int kc0  = (tid & 7) * 8;
    const __half* Ag = A  + (size_t)(bm + row0) * FIN + kc0;
    const __half* Bg = Bt + (size_t)(bn + row0) * FIN + kc0;

    uint32_t sbase = smem_u32(smh);
    uint32_t dA = sbase + (uint32_t)(row0 * TSH + kc0) * 2;
    uint32_t dB = sbase + (uint32_t)((128 + row0) * TSH + kc0) * 2;
    const uint32_t stageB  = STAGE_HALFS * 2;
    const uint32_t rowblkB = (uint32_t)(32 * TSH) * 2;
    const size_t   rowblkG = (size_t)32 * FIN;

    uint32_t laneAoff = (uint32_t)((wm * 64 + (q & 1) * 8 + lr) * TSH + (q >> 1) * 8) * 2;
    uint32_t laneBoff = (uint32_t)((128 + wn * 32 + (q >> 1) * 8 + lr) * TSH + (q & 1) * 8) * 2;

    float acc[4][4][4];
#pragma unroll
    for (int i = 0; i < 4; i++)
#pragma unroll
        for (int j = 0; j < 4; j++)
#pragma unroll
            for (int x = 0; x < 4; x++) acc[i][j][x] = 0.0f;

    const int NK = FIN / 64;  // 8 stages

#pragma unroll
    for (int s = 0; s < GSTAGES - 1; s++) {
        int k0 = s * 64;
        uint32_t so = s * stageB;
#pragma unroll
        for (int j = 0; j < 4; j++) {
            cp_async16(dA + so + j * rowblkB, Ag + j * rowblkG + k0);
            cp_async16(dB + so + j * rowblkB, Bg + j * rowblkG + k0);
        }
        CP_COMMIT();
    }
    CP_WAIT(GSTAGES - 2);

    int buf = 0, lbuf = GSTAGES - 1;
    for (int i = 0; i < NK; i++) {
        __syncthreads();

        if (i + GSTAGES - 1 < NK) {
            int k0 = (i + GSTAGES - 1) * 64;
            uint32_t so = lbuf * stageB;
#pragma unroll
            for (int j = 0; j < 4; j++) {
                cp_async16(dA + so + j * rowblkB, Ag + j * rowblkG + k0);
                cp_async16(dB + so + j * rowblkB, Bg + j * rowblkG + k0);
            }
        }
        CP_COMMIT();

        uint32_t sa = sbase + buf * stageB;
        uint32_t aA = sa + laneAoff;
        uint32_t aB = sa + laneBoff;
#pragma unroll
        for (int kk = 0; kk < 4; kk++) {
            uint32_t a[4][4];
            uint32_t b[2][4];
#pragma unroll
            for (int mt = 0; mt < 4; mt++)
                ldsm_x4(a[mt], aA + (uint32_t)(mt * 16 * TSH + kk * 16) * 2);
#pragma unroll
            for (int n2 = 0; n2 < 2; n2++)
                ldsm_x4(b[n2], aB + (uint32_t)(n2 * 16 * TSH + kk * 16) * 2);
#pragma unroll
            for (int mt = 0; mt < 4; mt++)
#pragma unroll
                for (int nt = 0; nt < 4; nt++)
                    mma_f16(acc[mt][nt][0], acc[mt][nt][1], acc[mt][nt][2], acc[mt][nt][3],
                            a[mt][0], a[mt][1], a[mt][2], a[mt][3],
                            b[nt >> 1][(nt & 1) * 2], b[nt >> 1][(nt & 1) * 2 + 1]);
        }

        CP_WAIT(GSTAGES - 2);
        buf  = (buf  == GSTAGES - 1) ? 0 : buf + 1;
        lbuf = (lbuf == GSTAGES - 1) ? 0 : lbuf + 1;
    }

#pragma unroll
    for (int mt = 0; mt < 4; mt++) {
        int mrow = bm + wm * 64 + mt * 16 + g;
#pragma unroll
        for (int nt = 0; nt < 4; nt++) {
            int ncol = bn + wn * 32 + nt * 8 + t * 2;
            __half2 lo = __floats2half2_rn(lrelu(acc[mt][nt][0]), lrelu(acc[mt][nt][1]));
            __half2 hi = __floats2half2_rn(lrelu(acc[mt][nt][2]), lrelu(acc[mt][nt][3]));
            *reinterpret_cast<__half2*>(C + (size_t)mrow * FOUT + ncol)       = lo;
            *reinterpret_cast<__half2*>(C + (size_t)(mrow + 8) * FOUT + ncol) = hi;
        }
    }
}

// ---------------- kernel 3: fused GAT softmax + multi-attention + BatchNorm ----------
// One block per node; processes BOTH passes; msg kept in smem; writes final output.
__global__ void gat_final_kernel(const __half* __restrict__ srczB,
                                 const __half* __restrict__ hzB,
                                 const float*  __restrict__ a0p,
                                 const float*  __restrict__ a1p,
                                 const float*  __restrict__ Wp1,
                                 const float*  __restrict__ bp1,
                                 const float*  __restrict__ Wp2,
                                 const float*  __restrict__ bp2,
                                 const float*  __restrict__ gamma,
                                 const float*  __restrict__ betaBN,
                                 const float*  __restrict__ mean,
                                 const float*  __restrict__ var,
                                 float*        __restrict__ out)
{
    int n   = blockIdx.x;
    int tid = threadIdx.x;  // 288 = 9 warps
    int warp = tid >> 5, lane = tid & 31;

    __shared__ __half zs[2][RR][FOUT];   // 16 KB
    __shared__ __half hzs[2][FOUT];      // 2 KB
    __shared__ float msgs[2][FOUT];      // 4 KB
    __shared__ float scoresm[2][9];
    __shared__ float alpha[2][RR];
    __shared__ float wred[4];
    __shared__ float betasm[2];

    // ---- load both passes' srcz (2*8*512 halfs) + hz ----
#pragma unroll
    for (int p = 0; p < 2; p++) {
        const uint4* zp = reinterpret_cast<const uint4*>(
            srczB + (size_t)p * NN * RR * FOUT + (size_t)n * RR * FOUT);
        uint4* zsm = reinterpret_cast<uint4*>(&zs[p][0][0]);
        for (int i = tid; i < RR * FOUT / 8; i += 288) zsm[i] = zp[i];
        const uint4* hp = reinterpret_cast<const uint4*>(
            hzB + (size_t)p * NN * FOUT + (size_t)n * FOUT);
        uint4* hsm = reinterpret_cast<uint4*>(&hzs[p][0]);
        for (int i = tid; i < FOUT / 8; i += 288) hsm[i] = hp[i];
    }
    __syncthreads();

    // ---- 18 dot products: warp w handles jobs w and w+9 ----
#pragma unroll
    for (int jj = 0; jj < 2; jj++) {
        int job = warp + jj * 9;          // 0..17
        int p   = job >= 9;
        int idx = job - p * 9;            // 0..8
        const __half* src = (idx < 8) ? &zs[p][idx][0] : &hzs[p][0];
        const float* av = (p ? a1p : a0p) + (idx < 8 ? 0 : FOUT);
        float s = 0.0f;
#pragma unroll
        for (int c = 0; c < 2; c++) {
            int base = (lane + c * 32) * 8;
            uint4 hv = *reinterpret_cast<const uint4*>(src + base);
            const __half2* hp2 = reinterpret_cast<const __half2*>(&hv);
            const float4* a4 = reinterpret_cast<const float4*>(av + base);
            float4 aa0 = a4[0], aa1 = a4[1];
            float2 z0 = __half22float2(hp2[0]);
            float2 z1 = __half22float2(hp2[1]);
            float2 z2 = __half22float2(hp2[2]);
            float2 z3 = __half22float2(hp2[3]);
            s += z0.x * aa0.x + z0.y * aa0.y + z1.x * aa0.z + z1.y * aa0.w;
            s += z2.x * aa1.x + z2.y * aa1.y + z3.x * aa1.z + z3.y * aa1.w;
        }
#pragma unroll
        for (int off = 16; off; off >>= 1)
            s += __shfl_down_sync(0xffffffffu, s, off);
        if (lane == 0) scoresm[p][idx] = s;
    }
    __syncthreads();

    // ---- per-pass softmax over relations (two threads in different warps) ----
    if (lane == 0 && warp < 2) {
        int p = warp;
        float sh = scoresm[p][8];
        float sc[RR], mx = -3.402823466e38f;
#pragma unroll
        for (int r = 0; r < RR; r++) {
            sc[r] = lrelu(scoresm[p][r] + sh);
            mx = fmaxf(mx, sc[r]);
        }
        float sum = 0.0f;
#pragma unroll
        for (int r = 0; r < RR; r++) {
            float e = expf(sc[r] - mx);
            alpha[p][r] = e;
            sum += e;
        }
        float inv = 1.0f / sum;
#pragma unroll
        for (int r = 0; r < RR; r++) alpha[p][r] *= inv;
    }
    __syncthreads();

    // ---- msg[p][f] in smem ----
    for (int f = tid; f < 2 * FOUT; f += 288) {
        int p  = f >> 9;
        int ff = f & (FOUT - 1);
        float acc = RESIDUAL * __half2float(hzs[p][ff]);
#pragma unroll
        for (int r = 0; r < RR; r++) acc += alpha[p][r] * __half2float(zs[p][r][ff]);
        msgs[p][ff] = acc;
    }
    __syncthreads();

    // ---- multi-attention matvec: threads 0-127 ----
    if (tid < 128) {
        int p  = tid >> 6;
        int hd = tid & 63;
        float acc = 0.0f;
#pragma unroll 8
        for (int k = 0; k < FOUT; k++) acc += msgs[p][k] * Wp1[k * HIDD + hd];
        float tt = tanhf(acc + bp1[hd]);
        float pw = tt * Wp2[hd];
#pragma unroll
        for (int off = 16; off; off >>= 1)
            pw += __shfl_down_sync(0xffffffffu, pw, off);
        if (lane == 0) wred[tid >> 5] = pw;
    }
    __syncthreads();
    if (tid == 0) {
        float w0 = tanhf(wred[0] + wred[1] + bp2[0]);
        float w1 = tanhf(wred[2] + wred[3] + bp2[0]);
        float m  = fmaxf(w0, w1);
        float e0 = expf(w0 - m), e1 = expf(w1 - m);
        float inv = 1.0f / (e0 + e1);
        betasm[0] = e0 * inv;
        betasm[1] = e1 * inv;
    }
    __syncthreads();

    // ---- BN + store ----
    float b0 = betasm[0], b1 = betasm[1];
    for (int f = tid; f < FOUT; f += 288) {
        float v = b0 * msgs[0][f] + b1 * msgs[1][f];
        out[(size_t)n * FOUT + f] =
            (v - mean[f]) * rsqrtf(var[f] + BN_EPS) * gamma[f] + betaBN[f];
    }
}

// ---------------- launch ----------------
extern "C" void kernel_launch(void* const* d_in, const int* in_sizes, int n_in,
                              void* d_out, int out_size)
{
    const float* src_h     = (const float*)d_in[0];
    const float* src_h_img = (const float*)d_in[1];
    const int*   rel       = (const int*)  d_in[2];
    const float* h         = (const float*)d_in[3];
    const float* h_img     = (const float*)d_in[4];
    const float* W0        = (const float*)d_in[5];
    const float* a0        = (const float*)d_in[6];
    const float* W1        = (const float*)d_in[7];
    const float* a1        = (const float*)d_in[8];
    const float* Wp1       = (const float*)d_in[9];
    const float* bp1       = (const float*)d_in[10];
    const float* Wp2       = (const float*)d_in[11];
    const float* bp2       = (const float*)d_in[12];
    const float* gamma     = (const float*)d_in[13];
    const float* betaBN    = (const float*)d_in[14];
    const float* mean      = (const float*)d_in[15];
    const float* var       = (const float*)d_in[16];
    float* out = (float*)d_out;

    __half *att, *wt, *hconv, *srcz, *hz;
    cudaGetSymbolAddress((void**)&att,   g_att);
    cudaGetSymbolAddress((void**)&srcz,  g_srcz);
    cudaGetSymbolAddress((void**)&hz,    g_hz);
    cudaGetSymbolAddress((void**)&wt,    g_wt);
    cudaGetSymbolAddress((void**)&hconv, g_hconv);

    static bool init_done = false;
    if (!init_done) {
        cudaFuncSetAttribute(gemm_tc_kernel,
                             cudaFuncAttributeMaxDynamicSharedMemorySize, GEMM_SMEM);
        init_done = true;
    }

    transposeW_kernel<<<dim3(16, 16, 2), dim3(32, 32)>>>(W0, W1, wt);
    convert_kernel<<<dim3((NN * FIN / 4 + 255) / 256, 2), 256>>>(h, h_img, hconv, NN * FIN / 4);
    maxpool_kernel<<<dim3(NN, 2), 128>>>(src_h, src_h_img, rel, att);
    gemm_tc_kernel<<<dim3(FOUT / 128, MBBIG + NN / 128, 2), 256, GEMM_SMEM>>>(
        att, hconv, wt, srcz, hz);
    gat_final_kernel<<<NN, 288>>>(srcz, hz, a0, a1,
                                  Wp1, bp1, Wp2, bp2,
                                  gamma, betaBN, mean, var, out);
}

// round 15
// speedup vs baseline: 1.0806x; 1.0806x over previous
#include <cuda_runtime.h>
#include <cuda_fp16.h>
#include <math.h>
#include <cstdint>

#define NN   16384
#define DD   16
#define FIN  512
#define FOUT 512
#define RR   8
#define HIDD 64
#define BN_EPS 1e-5f
#define RESIDUAL 0.12f

// ---------------- scratch (device globals: allocation-free), per-pass ----------------
__device__ __half g_att  [2ull * NN * RR * FIN];    // 268 MB (fp16)
__device__ __half g_srcz [2ull * NN * RR * FOUT];   // 268 MB (fp16)
__device__ __half g_hz   [2ull * NN * FOUT];        // 33 MB (fp16)
__device__ float  g_msg  [2ull * NN * FOUT];        // 67 MB
__device__ __half g_wt   [2ull * FIN * FOUT];       // 1 MB
__device__ __half g_hconv[2ull * NN * FIN];         // 34 MB

__device__ __forceinline__ float lrelu(float x) { return x >= 0.0f ? x : 0.2f * x; }

__device__ __forceinline__ uint32_t smem_u32(const void* p) {
    uint32_t a;
    asm("{ .reg .u64 t; cvta.to.shared.u64 t, %1; cvt.u32.u64 %0, t; }" : "=r"(a) : "l"(p));
    return a;
}
__device__ __forceinline__ void cp_async16(uint32_t dst, const void* src) {
    asm volatile("cp.async.cg.shared.global [%0], [%1], 16;" :: "r"(dst), "l"(src));
}
#define CP_COMMIT() asm volatile("cp.async.commit_group;" ::: "memory")
#define CP_WAIT(n)  asm volatile("cp.async.wait_group %0;" :: "n"(n) : "memory")

__device__ __forceinline__ void ldsm_x4(uint32_t* r, uint32_t addr) {
    asm volatile("ldmatrix.sync.aligned.m8n8.x4.shared.b16 {%0,%1,%2,%3}, [%4];"
        : "=r"(r[0]), "=r"(r[1]), "=r"(r[2]), "=r"(r[3]) : "r"(addr));
}

__device__ __forceinline__ void mma_f16(float& c0, float& c1, float& c2, float& c3,
                                        uint32_t a0, uint32_t a1, uint32_t a2, uint32_t a3,
                                        uint32_t b0, uint32_t b1) {
    asm volatile(
        "mma.sync.aligned.m16n8k16.row.col.f32.f16.f16.f32 "
        "{%0,%1,%2,%3}, {%4,%5,%6,%7}, {%8,%9}, {%0,%1,%2,%3};"
        : "+f"(c0), "+f"(c1), "+f"(c2), "+f"(c3)
        : "r"(a0), "r"(a1), "r"(a2), "r"(a3), "r"(b0), "r"(b1));
}

// ---------------- kernel 0a: transpose W [K,N] -> WT [N,K], fp16 (both passes) --------
__global__ void transposeW_kernel(const float* __restrict__ W0,
                                  const float* __restrict__ W1,
                                  __half* __restrict__ WT)
{
    int pass = blockIdx.z;
    const float* W = pass ? W1 : W0;
    __half* wt = WT + (size_t)pass * FIN * FOUT;
    __shared__ float t[32][33];
    int bx = blockIdx.x * 32, by = blockIdx.y * 32;
    t[threadIdx.y][threadIdx.x] = W[(by + threadIdx.y) * FOUT + bx + threadIdx.x];
    __syncthreads();
    wt[(bx + threadIdx.y) * FIN + by + threadIdx.x] = __float2half_rn(t[threadIdx.x][threadIdx.y]);
}

// ---------------- kernel 0b: convert h to fp16 (both passes) ----------------
__global__ void convert_kernel(const float* __restrict__ h0,
                               const float* __restrict__ h1,
                               __half* __restrict__ out, int n4)
{
    int pass = blockIdx.y;
    const float* in = pass ? h1 : h0;
    __half* o = out + (size_t)pass * NN * FIN;
    int i = blockIdx.x * blockDim.x + threadIdx.x;
    if (i < n4) {
        float4 v = reinterpret_cast<const float4*>(in)[i];
        __half2 hh0 = __floats2half2_rn(v.x, v.y);
        __half2 hh1 = __floats2half2_rn(v.z, v.w);
        uint2 st;
        st.x = *reinterpret_cast<uint32_t*>(&hh0);
        st.y = *reinterpret_cast<uint32_t*>(&hh1);
        reinterpret_cast<uint2*>(o)[i] = st;
    }
}

// ---------------- kernel 1: relation maxpool via counting sort (per pass) ------------
__global__ void maxpool_kernel(const float* __restrict__ src,
                               const int*   __restrict__ rel,
                               __half*      __restrict__ att)
{
    int n   = blockIdx.x;
    int tid = threadIdx.x;  // 128

    __shared__ int cnt[RR];
    __shared__ int ord[DD];
    __shared__ int relIdx[DD];
    __shared__ int isLast[DD];
    __shared__ int rl[DD];

    if (tid < RR) cnt[tid] = 0;
    __syncthreads();
    if (tid < DD) {
        int r = rel[n * DD + tid];
        rl[tid] = r;
        atomicAdd(&cnt[r], 1);
    }
    __syncthreads();
    if (tid == 0) {
        int pos[RR];
        int s = 0;
#pragma unroll
        for (int r = 0; r < RR; r++) { pos[r] = s; s += cnt[r]; }
#pragma unroll
        for (int d = 0; d < DD; d++) {
            int r = rl[d];
            int p = pos[r]++;
            ord[p] = d;
            relIdx[p] = r;
        }
#pragma unroll
        for (int i = 0; i < DD - 1; i++) isLast[i] = (relIdx[i + 1] != relIdx[i]);
        isLast[DD - 1] = 1;
    }
    __syncthreads();

    const float4* sp = reinterpret_cast<const float4*>(src + (size_t)n * DD * FIN);
    uint2* ap = reinterpret_cast<uint2*>(att + (size_t)n * RR * FIN);

    uint2 zz; zz.x = 0u; zz.y = 0u;
#pragma unroll
    for (int r = 0; r < RR; r++)
        if (cnt[r] == 0) ap[r * (FIN / 4) + tid] = zz;

    const float NEG = -3.402823466e38f;
    float4 acc = make_float4(NEG, NEG, NEG, NEG);

#pragma unroll
    for (int i = 0; i < DD; i++) {
        float4 v = sp[ord[i] * (FIN / 4) + tid];
        acc.x = fmaxf(acc.x, v.x);
        acc.y = fmaxf(acc.y, v.y);
        acc.z = fmaxf(acc.z, v.z);
        acc.w = fmaxf(acc.w, v.w);
        if (isLast[i]) {
            int r = relIdx[i];
            float4 o = acc;
            if (cnt[r] != DD) {
                o.x = fmaxf(o.x, 0.0f);
                o.y = fmaxf(o.y, 0.0f);
                o.z = fmaxf(o.z, 0.0f);
                o.w = fmaxf(o.w, 0.0f);
            }
            __half2 h0 = __floats2half2_rn(o.x, o.y);
            __half2 h1 = __floats2half2_rn(o.z, o.w);
            uint2 st;
            st.x = *reinterpret_cast<uint32_t*>(&h0);
            st.y = *reinterpret_cast<uint32_t*>(&h1);
            ap[r * (FIN / 4) + tid] = st;
            acc = make_float4(NEG, NEG, NEG, NEG);
        }
    }
}

// ---------------- kernel 2: mma.sync fp16 GEMM (per pass) -------
// blocks y<1024: srcz = lrelu(att @ WT^T); y>=1024: hz from hconv.
// BM=128, BN=128, BK=64. 256 threads, 8 warps (2M x 4N), warp tile 64x32.
#define TSH 72
#define STAGE_HALFS ((128 + 128) * TSH)
#define GSTAGES 3
#define GEMM_SMEM (GSTAGES * STAGE_HALFS * 2)    // 110592 bytes
#define MBBIG (NN * RR / 128)

__global__ void __launch_bounds__(256, 2)
gemm_tc_kernel(const __half* __restrict__ attP,
               const __half* __restrict__ hconvP,
               const __half* __restrict__ Bt,
               __half*       __restrict__ srczP,
               __half*       __restrict__ hzP)
{
    extern __shared__ __half smh[];
    int tid  = threadIdx.x;
    int wid  = tid >> 5;
    int lane = tid & 31;
    int wm   = wid & 1;
    int wn   = wid >> 1;
    int g    = lane >> 2;
    int t    = lane & 3;
    int q    = lane >> 3;
    int lr   = lane & 7;

    int mb = blockIdx.y;
    const __half* A;
    __half* C;
    int bm;
    if (mb < MBBIG) { A = attP;   C = srczP; bm = mb * 128; }
    else            { A = hconvP; C = hzP;   bm = (mb - MBBIG) * 128; }
    int bn = blockIdx.x * 128;

    int row0 = tid >> 3;
    int kc0  = (tid & 7) * 8;
    const __half* Ag = A  + (size_t)(bm + row0) * FIN + kc0;
    const __half* Bg = Bt + (size_t)(bn + row0) * FIN + kc0;

    uint32_t sbase = smem_u32(smh);
    uint32_t dA = sbase + (uint32_t)(row0 * TSH + kc0) * 2;
    uint32_t dB = sbase + (uint32_t)((128 + row0) * TSH + kc0) * 2;
    const uint32_t stageB  = STAGE_HALFS * 2;
    const uint32_t rowblkB = (uint32_t)(32 * TSH) * 2;
    const size_t   rowblkG = (size_t)32 * FIN;

    uint32_t laneAoff = (uint32_t)((wm * 64 + (q & 1) * 8 + lr) * TSH + (q >> 1) * 8) * 2;
    uint32_t laneBoff = (uint32_t)((128 + wn * 32 + (q >> 1) * 8 + lr) * TSH + (q & 1) * 8) * 2;

    float acc[4][4][4];
#pragma unroll
    for (int i = 0; i < 4; i++)
#pragma unroll
        for (int j = 0; j < 4; j++)
#pragma unroll
            for (int x = 0; x < 4; x++) acc[i][j][x] = 0.0f;

    const int NK = FIN / 64;  // 8 stages

#pragma unroll
    for (int s = 0; s < GSTAGES - 1; s++) {
        int k0 = s * 64;
        uint32_t so = s * stageB;
#pragma unroll
        for (int j = 0; j < 4; j++) {
            cp_async16(dA + so + j * rowblkB, Ag + j * rowblkG + k0);
            cp_async16(dB + so + j * rowblkB, Bg + j * rowblkG + k0);
        }
        CP_COMMIT();
    }
    CP_WAIT(GSTAGES - 2);

    int buf = 0, lbuf = GSTAGES - 1;
    for (int i = 0; i < NK; i++) {
        __syncthreads();

        if (i + GSTAGES - 1 < NK) {
            int k0 = (i + GSTAGES - 1) * 64;
            uint32_t so = lbuf * stageB;
#pragma unroll
            for (int j = 0; j < 4; j++) {
                cp_async16(dA + so + j * rowblkB, Ag + j * rowblkG + k0);
                cp_async16(dB + so + j * rowblkB, Bg + j * rowblkG + k0);
            }
        }
        CP_COMMIT();

        uint32_t sa = sbase + buf * stageB;
        uint32_t aA = sa + laneAoff;
        uint32_t aB = sa + laneBoff;
#pragma unroll
        for (int kk = 0; kk < 4; kk++) {
            uint32_t a[4][4];
            uint32_t b[2][4];
#pragma unroll
            for (int mt = 0; mt < 4; mt++)
                ldsm_x4(a[mt], aA + (uint32_t)(mt * 16 * TSH + kk * 16) * 2);
#pragma unroll
            for (int n2 = 0; n2 < 2; n2++)
                ldsm_x4(b[n2], aB + (uint32_t)(n2 * 16 * TSH + kk * 16) * 2);
#pragma unroll
            for (int mt = 0; mt < 4; mt++)
#pragma unroll
                for (int nt = 0; nt < 4; nt++)
                    mma_f16(acc[mt][nt][0], acc[mt][nt][1], acc[mt][nt][2], acc[mt][nt][3],
                            a[mt][0], a[mt][1], a[mt][2], a[mt][3],
                            b[nt >> 1][(nt & 1) * 2], b[nt >> 1][(nt & 1) * 2 + 1]);
        }

        CP_WAIT(GSTAGES - 2);
        buf  = (buf  == GSTAGES - 1) ? 0 : buf + 1;
        lbuf = (lbuf == GSTAGES - 1) ? 0 : lbuf + 1;
    }

#pragma unroll
    for (int mt = 0; mt < 4; mt++) {
        int mrow = bm + wm * 64 + mt * 16 + g;
#pragma unroll
        for (int nt = 0; nt < 4; nt++) {
            int ncol = bn + wn * 32 + nt * 8 + t * 2;
            __half2 lo = __floats2half2_rn(lrelu(acc[mt][nt][0]), lrelu(acc[mt][nt][1]));
            __half2 hi = __floats2half2_rn(lrelu(acc[mt][nt][2]), lrelu(acc[mt][nt][3]));
            *reinterpret_cast<__half2*>(C + (size_t)mrow * FOUT + ncol)       = lo;
            *reinterpret_cast<__half2*>(C + (size_t)(mrow + 8) * FOUT + ncol) = hi;
        }
    }
}

// ---------------- kernel 3: GAT softmax epilogue (per pass) ----------
__global__ void gat_epilogue_kernel(const __half* __restrict__ srcz,
                                    const __half* __restrict__ hz,
                                    const float*  __restrict__ a_attn,
                                    float*        __restrict__ msg)
{
    int n   = blockIdx.x;
    int tid = threadIdx.x;  // 288 = 9 warps
    int warp = tid >> 5, lane = tid & 31;

    __shared__ __half zs[RR][FOUT];
    __shared__ __half hzs[FOUT];
    __shared__ float scoresm[9];
    __shared__ float alpha[RR];

    const uint4* zp = reinterpret_cast<const uint4*>(srcz + (size_t)n * RR * FOUT);
    uint4* zsm = reinterpret_cast<uint4*>(&zs[0][0]);
    for (int i = tid; i < RR * FOUT / 8; i += 288) zsm[i] = zp[i];
    const uint4* hp = reinterpret_cast<const uint4*>(hz + (size_t)n * FOUT);
    uint4* hsm = reinterpret_cast<uint4*>(hzs);
    for (int i = tid; i < FOUT / 8; i += 288) hsm[i] = hp[i];
    __syncthreads();

    {
        const __half* src = (warp < 8) ? &zs[warp][0] : hzs;
        const float* av = a_attn + (warp < 8 ? 0 : FOUT);
        float s = 0.0f;
#pragma unroll
        for (int c = 0; c < 2; c++) {
            int base = (lane + c * 32) * 8;
            uint4 hv = *reinterpret_cast<const uint4*>(src + base);
            const __half2* hp2 = reinterpret_cast<const __half2*>(&hv);
            const float4* a4 = reinterpret_cast<const float4*>(av + base);
            float4 aa0 = a4[0], aa1 = a4[1];
            float2 z0 = __half22float2(hp2[0]);
            float2 z1 = __half22float2(hp2[1]);
            float2 z2 = __half22float2(hp2[2]);
            float2 z3 = __half22float2(hp2[3]);
            s += z0.x * aa0.x + z0.y * aa0.y + z1.x * aa0.z + z1.y * aa0.w;
            s += z2.x * aa1.x + z2.y * aa1.y + z3.x * aa1.z + z3.y * aa1.w;
        }
#pragma unroll
        for (int off = 16; off; off >>= 1)
            s += __shfl_down_sync(0xffffffffu, s, off);
        if (lane == 0) scoresm[warp] = s;
    }
    __syncthreads();

    if (tid == 0) {
        float sh = scoresm[8];
        float sc[RR], mx = -3.402823466e38f;
#pragma unroll
        for (int r = 0; r < RR; r++) {
            sc[r] = lrelu(scoresm[r] + sh);
            mx = fmaxf(mx, sc[r]);
        }
        float sum = 0.0f;
#pragma unroll
        for (int r = 0; r < RR; r++) {
            float e = expf(sc[r] - mx);
            alpha[r] = e;
            sum += e;
        }
        float inv = 1.0f / sum;
#pragma unroll
        for (int r = 0; r < RR; r++) alpha[r] *= inv;
    }
    __syncthreads();

    float al[RR];
#pragma unroll
    for (int r = 0; r < RR; r++) al[r] = alpha[r];

    for (int f = tid; f < FOUT; f += 288) {
        float acc = RESIDUAL * __half2float(hzs[f]);
#pragma unroll
        for (int r = 0; r < RR; r++) acc += al[r] * __half2float(zs[r][f]);
        msg[(size_t)n * FOUT + f] = acc;
    }
}

// ---------------- kernel 4: multi-attention + BatchNorm ----------------
__global__ void final_kernel(const float* __restrict__ Wp1,
                             const float* __restrict__ bp1,
                             const float* __restrict__ Wp2,
                             const float* __restrict__ bp2,
                             const float* __restrict__ gamma,
                             const float* __restrict__ betaBN,
                             const float* __restrict__ mean,
                             const float* __restrict__ var,
                             float*       __restrict__ out)
{
    int n   = blockIdx.x;
    int tid = threadIdx.x;  // 128

    __shared__ float z[2][FOUT];
    __shared__ float wred[4];
    __shared__ float betasm[2];

    for (int f = tid; f < FOUT; f += 128) {
        z[0][f] = g_msg[(size_t)n * FOUT + f];
        z[1][f] = g_msg[(size_t)NN * FOUT + (size_t)n * FOUT + f];
    }
    __syncthreads();

    int i  = tid >> 6;
    int hd = tid & 63;
    float acc = 0.0f;
#pragma unroll 8
    for (int k = 0; k < FOUT; k++) acc += z[i][k] * Wp1[k * HIDD + hd];
    float t  = tanhf(acc + bp1[hd]);
    float pw = t * Wp2[hd];

#pragma unroll
    for (int off = 16; off; off >>= 1)
        pw += __shfl_down_sync(0xffffffffu, pw, off);
    if ((tid & 31) == 0) wred[tid >> 5] = pw;
    __syncthreads();
    if (tid == 0) {
        float w0 = tanhf(wred[0] + wred[1] + bp2[0]);
        float w1 = tanhf(wred[2] + wred[3] + bp2[0]);
        float m  = fmaxf(w0, w1);
        float e0 = expf(w0 - m), e1 = expf(w1 - m);
        float inv = 1.0f / (e0 + e1);
        betasm[0] = e0 * inv;
        betasm[1] = e1 * inv;
    }
    __syncthreads();

    float b0 = betasm[0], b1 = betasm[1];
    for (int f = tid; f < FOUT; f += 128) {
        float v = b0 * z[0][f] + b1 * z[1][f];
        out[(size_t)n * FOUT + f] =
            (v - mean[f]) * rsqrtf(var[f] + BN_EPS) * gamma[f] + betaBN[f];
    }
}

// ---------------- launch: skewed two-stream pipeline ----------------
extern "C" void kernel_launch(void* const* d_in, const int* in_sizes, int n_in,
                              void* d_out, int out_size)
{
    const float* src_h     = (const float*)d_in[0];
    const float* src_h_img = (const float*)d_in[1];
    const int*   rel       = (const int*)  d_in[2];
    const float* h         = (const float*)d_in[3];
    const float* h_img     = (const float*)d_in[4];
    const float* W0        = (const float*)d_in[5];
    const float* a0        = (const float*)d_in[6];
    const float* W1        = (const float*)d_in[7];
    const float* a1        = (const float*)d_in[8];
    const float* Wp1       = (const float*)d_in[9];
    const float* bp1       = (const float*)d_in[10];
    const float* Wp2       = (const float*)d_in[11];
    const float* bp2       = (const float*)d_in[12];
    const float* gamma     = (const float*)d_in[13];
    const float* betaBN    = (const float*)d_in[14];
    const float* mean      = (const float*)d_in[15];
    const float* var       = (const float*)d_in[16];
    float* out = (float*)d_out;

    __half *att, *wt, *hconv, *srcz, *hz;
    float *msg;
    cudaGetSymbolAddress((void**)&att,   g_att);
    cudaGetSymbolAddress((void**)&srcz,  g_srcz);
    cudaGetSymbolAddress((void**)&hz,    g_hz);
    cudaGetSymbolAddress((void**)&msg,   g_msg);
    cudaGetSymbolAddress((void**)&wt,    g_wt);
    cudaGetSymbolAddress((void**)&hconv, g_hconv);

    static cudaStream_t s1 = nullptr;
    static cudaEvent_t eMp0 = nullptr, eMp1 = nullptr, eG0 = nullptr, eGat0 = nullptr;
    if (!s1) {
        cudaStreamCreateWithFlags(&s1, cudaStreamNonBlocking);
        cudaEventCreateWithFlags(&eMp0,  cudaEventDisableTiming);
        cudaEventCreateWithFlags(&eMp1,  cudaEventDisableTiming);
        cudaEventCreateWithFlags(&eG0,   cudaEventDisableTiming);
        cudaEventCreateWithFlags(&eGat0, cudaEventDisableTiming);
        cudaFuncSetAttribute(gemm_tc_kernel,
                             cudaFuncAttributeMaxDynamicSharedMemorySize, GEMM_SMEM);
    }

    __half* att0   = att;                          __half* att1   = att   + (size_t)NN * RR * FIN;
    __half* wt0    = wt;                           __half* wt1    = wt    + (size_t)FIN * FOUT;
    __half* hconv0 = hconv;                        __half* hconv1 = hconv + (size_t)NN * FIN;
    __half* srcz0  = srcz;                         __half* srcz1  = srcz  + (size_t)NN * RR * FOUT;
    __half* hz0    = hz;                           __half* hz1    = hz    + (size_t)NN * FOUT;
    float*  msg0   = msg;                          float*  msg1   = msg   + (size_t)NN * FOUT;

    dim3 gemm_grid(FOUT / 128, MBBIG + NN / 128);

    // stream 0: setup + pass-0 chain
    transposeW_kernel<<<dim3(16, 16, 2), dim3(32, 32)>>>(W0, W1, wt);
    convert_kernel<<<dim3((NN * FIN / 4 + 255) / 256, 2), 256>>>(h, h_img, hconv, NN * FIN / 4);
    maxpool_kernel<<<NN, 128>>>(src_h, rel, att0);
    cudaEventRecord(eMp0, 0);
    gemm_tc_kernel<<<gemm_grid, 256, GEMM_SMEM>>>(att0, hconv0, wt0, srcz0, hz0);
    cudaEventRecord(eG0, 0);

    // stream 1: maxpool pass-1 overlaps gemm pass-0; gat pass-0 overlaps gemm pass-1
    cudaStreamWaitEvent(s1, eMp0, 0);
    maxpool_kernel<<<NN, 128, 0, s1>>>(src_h_img, rel, att1);
    cudaEventRecord(eMp1, s1);
    cudaStreamWaitEvent(s1, eG0, 0);
    gat_epilogue_kernel<<<NN, 288, 0, s1>>>(srcz0, hz0, a0, msg0);
    cudaEventRecord(eGat0, s1);

    // stream 0: gemm pass-1 (needs mp1), then gat pass-1, join, final
    cudaStreamWaitEvent((cudaStream_t)0, eMp1, 0);
    gemm_tc_kernel<<<gemm_grid, 256, GEMM_SMEM>>>(att1, hconv1, wt1, srcz1, hz1);
    gat_epilogue_kernel<<<NN, 288>>>(srcz1, hz1, a1, msg1);
    cudaStreamWaitEvent((cudaStream_t)0, eGat0, 0);
    final_kernel<<<NN, 128>>>(Wp1, bp1, Wp2, bp2, gamma, betaBN, mean, var, out);
}

// round 16
// speedup vs baseline: 1.0987x; 1.0168x over previous
#include <cuda_runtime.h>
#include <cuda_fp16.h>
#include <math.h>
#include <cstdint>

#define NN   16384
#define DD   16
#define FIN  512
#define FOUT 512
#define RR   8
#define HIDD 64
#define BN_EPS 1e-5f
#define RESIDUAL 0.12f

// ---------------- scratch (device globals: allocation-free), per-pass ----------------
__device__ __half g_att  [2ull * NN * RR * FIN];    // 268 MB (fp16)
__device__ __half g_srcz [2ull * NN * RR * FOUT];   // 268 MB (fp16)
__device__ __half g_hz   [2ull * NN * FOUT];        // 33 MB (fp16)
__device__ __half g_msg  [2ull * NN * FOUT];        // 33 MB (fp16)
__device__ __half g_wt   [2ull * FIN * FOUT];       // 1 MB

__device__ __forceinline__ float lrelu(float x) { return x >= 0.0f ? x : 0.2f * x; }

__device__ __forceinline__ uint32_t smem_u32(const void* p) {
    uint32_t a;
    asm("{ .reg .u64 t; cvta.to.shared.u64 t, %1; cvt.u32.u64 %0, t; }" : "=r"(a) : "l"(p));
    return a;
}
__device__ __forceinline__ void cp_async16(uint32_t dst, const void* src) {
    asm volatile("cp.async.cg.shared.global [%0], [%1], 16;" :: "r"(dst), "l"(src));
}
#define CP_COMMIT() asm volatile("cp.async.commit_group;" ::: "memory")
#define CP_WAIT(n)  asm volatile("cp.async.wait_group %0;" :: "n"(n) : "memory")

__device__ __forceinline__ void ldsm_x4(uint32_t* r, uint32_t addr) {
    asm volatile("ldmatrix.sync.aligned.m8n8.x4.shared.b16 {%0,%1,%2,%3}, [%4];"
        : "=r"(r[0]), "=r"(r[1]), "=r"(r[2]), "=r"(r[3]) : "r"(addr));
}

__device__ __forceinline__ void mma_f16(float& c0, float& c1, float& c2, float& c3,
                                        uint32_t a0, uint32_t a1, uint32_t a2, uint32_t a3,
                                        uint32_t b0, uint32_t b1) {
    asm volatile(
        "mma.sync.aligned.m16n8k16.row.col.f32.f16.f16.f32 "
        "{%0,%1,%2,%3}, {%4,%5,%6,%7}, {%8,%9}, {%0,%1,%2,%3};"
        : "+f"(c0), "+f"(c1), "+f"(c2), "+f"(c3)
        : "r"(a0), "r"(a1), "r"(a2), "r"(a3), "r"(b0), "r"(b1));
}

// fp32x8 -> fp16x8 convert + 16B shared store (for the h operand path)
__device__ __forceinline__ void load_A_h(uint32_t dst, const float* src) {
    float4 v0 = *reinterpret_cast<const float4*>(src);
    float4 v1 = *reinterpret_cast<const float4*>(src + 4);
    __half2 p0 = __floats2half2_rn(v0.x, v0.y);
    __half2 p1 = __floats2half2_rn(v0.z, v0.w);
    __half2 p2 = __floats2half2_rn(v1.x, v1.y);
    __half2 p3 = __floats2half2_rn(v1.z, v1.w);
    asm volatile("st.shared.v4.b32 [%0], {%1,%2,%3,%4};"
        :: "r"(dst),
           "r"(*reinterpret_cast<uint32_t*>(&p0)), "r"(*reinterpret_cast<uint32_t*>(&p1)),
           "r"(*reinterpret_cast<uint32_t*>(&p2)), "r"(*reinterpret_cast<uint32_t*>(&p3))
        : "memory");
}

// ---------------- kernel 0: transpose W [K,N] -> WT [N,K], fp16 (both passes) --------
__global__ void transposeW_kernel(const float* __restrict__ W0,
                                  const float* __restrict__ W1,
                                  __half* __restrict__ WT)
{
    int pass = blockIdx.z;
    const float* W = pass ? W1 : W0;
    __half* wt = WT + (size_t)pass * FIN * FOUT;
    __shared__ float t[32][33];
    int bx = blockIdx.x * 32, by = blockIdx.y * 32;
    t[threadIdx.y][threadIdx.x] = W[(by + threadIdx.y) * FOUT + bx + threadIdx.x];
    __syncthreads();
    wt[(bx + threadIdx.y) * FIN + by + threadIdx.x] = __float2half_rn(t[threadIdx.x][threadIdx.y]);
}

// ---------------- kernel 1: relation maxpool via counting sort (both passes) ---------
__global__ void maxpool_kernel(const float* __restrict__ src0,
                               const float* __restrict__ src1,
                               const int*   __restrict__ rel,
                               __half*      __restrict__ attBase)
{
    int n    = blockIdx.x;
    int pass = blockIdx.y;
    const float* src = pass ? src1 : src0;
    __half* att = attBase + (size_t)pass * NN * RR * FIN;
    int tid = threadIdx.x;  // 128

    __shared__ int cnt[RR];
    __shared__ int ord[DD];
    __shared__ int relIdx[DD];
    __shared__ int isLast[DD];
    __shared__ int rl[DD];

    if (tid < RR) cnt[tid] = 0;
    __syncthreads();
    if (tid < DD) {
        int r = rel[n * DD + tid];
        rl[tid] = r;
        atomicAdd(&cnt[r], 1);
    }
    __syncthreads();
    if (tid == 0) {
        int pos[RR];
        int s = 0;
#pragma unroll
        for (int r = 0; r < RR; r++) { pos[r] = s; s += cnt[r]; }
#pragma unroll
        for (int d = 0; d < DD; d++) {
            int r = rl[d];
            int p = pos[r]++;
            ord[p] = d;
            relIdx[p] = r;
        }
#pragma unroll
        for (int i = 0; i < DD - 1; i++) isLast[i] = (relIdx[i + 1] != relIdx[i]);
        isLast[DD - 1] = 1;
    }
    __syncthreads();

    const float4* sp = reinterpret_cast<const float4*>(src + (size_t)n * DD * FIN);
    uint2* ap = reinterpret_cast<uint2*>(att + (size_t)n * RR * FIN);

    uint2 zz; zz.x = 0u; zz.y = 0u;
#pragma unroll
    for (int r = 0; r < RR; r++)
        if (cnt[r] == 0) ap[r * (FIN / 4) + tid] = zz;

    const float NEG = -3.402823466e38f;
    float4 acc = make_float4(NEG, NEG, NEG, NEG);

#pragma unroll
    for (int i = 0; i < DD; i++) {
        float4 v = sp[ord[i] * (FIN / 4) + tid];
        acc.x = fmaxf(acc.x, v.x);
        acc.y = fmaxf(acc.y, v.y);
        acc.z = fmaxf(acc.z, v.z);
        acc.w = fmaxf(acc.w, v.w);
        if (isLast[i]) {
            int r = relIdx[i];
            float4 o = acc;
            if (cnt[r] != DD) {
                o.x = fmaxf(o.x, 0.0f);
                o.y = fmaxf(o.y, 0.0f);
                o.z = fmaxf(o.z, 0.0f);
                o.w = fmaxf(o.w, 0.0f);
            }
            __half2 h0 = __floats2half2_rn(o.x, o.y);
            __half2 h1 = __floats2half2_rn(o.z, o.w);
            uint2 st;
            st.x = *reinterpret_cast<uint32_t*>(&h0);
            st.y = *reinterpret_cast<uint32_t*>(&h1);
            ap[r * (FIN / 4) + tid] = st;
            acc = make_float4(NEG, NEG, NEG, NEG);
        }
    }
}

// ---------------- kernel 2: mma.sync fp16 GEMM (both passes via z) -------
// blocks y<1024: srcz = lrelu(att @ WT^T); y>=1024: hz from fp32 h (converted in-loader).
// BM=128, BN=128, BK=64. 256 threads, 8 warps (2M x 4N), warp tile 64x32. 3-stage ring.
#define TSH 72
#define STAGE_HALFS ((128 + 128) * TSH)
#define GSTAGES 3
#define GEMM_SMEM (GSTAGES * STAGE_HALFS * 2)    // 110592 bytes
#define MBBIG (NN * RR / 128)

__global__ void __launch_bounds__(256, 2)
gemm_tc_kernel(const __half* __restrict__ attB,
               const float*  __restrict__ h0,
               const float*  __restrict__ h1,
               const __half* __restrict__ wtB,
               __half*       __restrict__ srczB,
               __half*       __restrict__ hzB)
{
    extern __shared__ __half smh[];
    int tid  = threadIdx.x;
    int wid  = tid >> 5;
    int lane = tid & 31;
    int wm   = wid & 1;
    int wn   = wid >> 1;
    int g    = lane >> 2;
    int t    = lane & 3;
    int q    = lane >> 3;
    int lr   = lane & 7;

    int pass = blockIdx.z;
    const __half* Bt = wtB + (size_t)pass * FIN * FOUT;

    int mb = blockIdx.y;
    bool isH = (mb >= MBBIG);
    __half* C;
    int bm;
    const __half* Ahalf = nullptr;
    const float*  Hsrc  = nullptr;
    if (!isH) {
        Ahalf = attB + (size_t)pass * NN * RR * FIN;
        C     = srczB + (size_t)pass * NN * RR * FOUT;
        bm    = mb * 128;
    } else {
        Hsrc  = pass ? h1 : h0;
        C     = hzB + (size_t)pass * NN * FOUT;
        bm    = (mb - MBBIG) * 128;
    }
    int bn = blockIdx.x * 128;

    int row0 = tid >> 3;              // 0..31
    int kc0  = (tid & 7) * 8;         // element offset 0..56
    const __half* Ag = isH ? nullptr : Ahalf + (size_t)(bm + row0) * FIN + kc0;
    const float*  Hg = isH ? Hsrc + (size_t)(bm + row0) * FIN + kc0 : nullptr;
    const __half* Bg = Bt + (size_t)(bn + row0) * FIN + kc0;

    uint32_t sbase = smem_u32(smh);
    uint32_t dA = sbase + (uint32_t)(row0 * TSH + kc0) * 2;
    uint32_t dB = sbase + (uint32_t)((128 + row0) * TSH + kc0) * 2;
    const uint32_t stageB  = STAGE_HALFS * 2;
    const uint32_t rowblkB = (uint32_t)(32 * TSH) * 2;
    const size_t   rowblkG = (size_t)32 * FIN;

    uint32_t laneAoff = (uint32_t)((wm * 64 + (q & 1) * 8 + lr) * TSH + (q >> 1) * 8) * 2;
    uint32_t laneBoff = (uint32_t)((128 + wn * 32 + (q >> 1) * 8 + lr) * TSH + (q & 1) * 8) * 2;

    float acc[4][4][4];
#pragma unroll
    for (int i = 0; i < 4; i++)
#pragma unroll
        for (int j = 0; j < 4; j++)
#pragma unroll
            for (int x = 0; x < 4; x++) acc[i][j][x] = 0.0f;

    const int NK = FIN / 64;  // 8 stages

#pragma unroll
    for (int s = 0; s < GSTAGES - 1; s++) {
        int k0 = s * 64;
        uint32_t so = s * stageB;
#pragma unroll
        for (int j = 0; j < 4; j++) {
            if (!isH) cp_async16(dA + so + j * rowblkB, Ag + j * rowblkG + k0);
            else      load_A_h (dA + so + j * rowblkB, Hg + j * rowblkG + k0);
            cp_async16(dB + so + j * rowblkB, Bg + j * rowblkG + k0);
        }
        CP_COMMIT();
    }
    CP_WAIT(GSTAGES - 2);

    int buf = 0, lbuf = GSTAGES - 1;
    for (int i = 0; i < NK; i++) {
        __syncthreads();

        if (i + GSTAGES - 1 < NK) {
            int k0 = (i + GSTAGES - 1) * 64;
            uint32_t so = lbuf * stageB;
#pragma unroll
            for (int j = 0; j < 4; j++) {
                if (!isH) cp_async16(dA + so + j * rowblkB, Ag + j * rowblkG + k0);
                else      load_A_h (dA + so + j * rowblkB, Hg + j * rowblkG + k0);
                cp_async16(dB + so + j * rowblkB, Bg + j * rowblkG + k0);
            }
        }
        CP_COMMIT();

        uint32_t sa = sbase + buf * stageB;
        uint32_t aA = sa + laneAoff;
        uint32_t aB = sa + laneBoff;
#pragma unroll
        for (int kk = 0; kk < 4; kk++) {
            uint32_t a[4][4];
            uint32_t b[2][4];
#pragma unroll
            for (int mt = 0; mt < 4; mt++)
                ldsm_x4(a[mt], aA + (uint32_t)(mt * 16 * TSH + kk * 16) * 2);
#pragma unroll
            for (int n2 = 0; n2 < 2; n2++)
                ldsm_x4(b[n2], aB + (uint32_t)(n2 * 16 * TSH + kk * 16) * 2);
#pragma unroll
            for (int mt = 0; mt < 4; mt++)
#pragma unroll
                for (int nt = 0; nt < 4; nt++)
                    mma_f16(acc[mt][nt][0], acc[mt][nt][1], acc[mt][nt][2], acc[mt][nt][3],
                            a[mt][0], a[mt][1], a[mt][2], a[mt][3],
                            b[nt >> 1][(nt & 1) * 2], b[nt >> 1][(nt & 1) * 2 + 1]);
        }

        CP_WAIT(GSTAGES - 2);
        buf  = (buf  == GSTAGES - 1) ? 0 : buf + 1;
        lbuf = (lbuf == GSTAGES - 1) ? 0 : lbuf + 1;
    }

    // ---- epilogue: lrelu + fp16 store ----
#pragma unroll
    for (int mt = 0; mt < 4; mt++) {
        int mrow = bm + wm * 64 + mt * 16 + g;
#pragma unroll
        for (int nt = 0; nt < 4; nt++) {
            int ncol = bn + wn * 32 + nt * 8 + t * 2;
            __half2 lo = __floats2half2_rn(lrelu(acc[mt][nt][0]), lrelu(acc[mt][nt][1]));
            __half2 hi = __floats2half2_rn(lrelu(acc[mt][nt][2]), lrelu(acc[mt][nt][3]));
            *reinterpret_cast<__half2*>(C + (size_t)mrow * FOUT + ncol)       = lo;
            *reinterpret_cast<__half2*>(C + (size_t)(mrow + 8) * FOUT + ncol) = hi;
        }
    }
}

// ---------------- kernel 3: GAT softmax epilogue (fp16 in/out, both passes) ----------
__global__ void gat_epilogue_kernel(const __half* __restrict__ srczB,
                                    const __half* __restrict__ hzB,
                                    const float*  __restrict__ a0p,
                                    const float*  __restrict__ a1p,
                                    __half*       __restrict__ msgB)
{
    int n    = blockIdx.x;
    int pass = blockIdx.y;
    const __half* srcz = srczB + (size_t)pass * NN * RR * FOUT;
    const __half* hz   = hzB   + (size_t)pass * NN * FOUT;
    const float* a_attn = pass ? a1p : a0p;
    __half* msg = msgB + (size_t)pass * NN * FOUT;

    int tid = threadIdx.x;  // 288 = 9 warps
    int warp = tid >> 5, lane = tid & 31;

    __shared__ __half zs[RR][FOUT];
    __shared__ __half hzs[FOUT];
    __shared__ float scoresm[9];
    __shared__ float alpha[RR];

    const uint4* zp = reinterpret_cast<const uint4*>(srcz + (size_t)n * RR * FOUT);
    uint4* zsm = reinterpret_cast<uint4*>(&zs[0][0]);
    for (int i = tid; i < RR * FOUT / 8; i += 288) zsm[i] = zp[i];
    const uint4* hp = reinterpret_cast<const uint4*>(hz + (size_t)n * FOUT);
    uint4* hsm = reinterpret_cast<uint4*>(hzs);
    for (int i = tid; i < FOUT / 8; i += 288) hsm[i] = hp[i];
    __syncthreads();

    {
        const __half* src = (warp < 8) ? &zs[warp][0] : hzs;
        const float* av = a_attn + (warp < 8 ? 0 : FOUT);
        float s = 0.0f;
#pragma unroll
        for (int c = 0; c < 2; c++) {
            int base = (lane + c * 32) * 8;
            uint4 hv = *reinterpret_cast<const uint4*>(src + base);
            const __half2* hp2 = reinterpret_cast<const __half2*>(&hv);
            const float4* a4 = reinterpret_cast<const float4*>(av + base);
            float4 aa0 = a4[0], aa1 = a4[1];
            float2 z0 = __half22float2(hp2[0]);
            float2 z1 = __half22float2(hp2[1]);
            float2 z2 = __half22float2(hp2[2]);
            float2 z3 = __half22float2(hp2[3]);
            s += z0.x * aa0.x + z0.y * aa0.y + z1.x * aa0.z + z1.y * aa0.w;
            s += z2.x * aa1.x + z2.y * aa1.y + z3.x * aa1.z + z3.y * aa1.w;
        }
#pragma unroll
        for (int off = 16; off; off >>= 1)
            s += __shfl_down_sync(0xffffffffu, s, off);
        if (lane == 0) scoresm[warp] = s;
    }
    __syncthreads();

    if (tid == 0) {
        float sh = scoresm[8];
        float sc[RR], mx = -3.402823466e38f;
#pragma unroll
        for (int r = 0; r < RR; r++) {
            sc[r] = lrelu(scoresm[r] + sh);
            mx = fmaxf(mx, sc[r]);
        }
        float sum = 0.0f;
#pragma unroll
        for (int r = 0; r < RR; r++) {
            float e = expf(sc[r] - mx);
            alpha[r] = e;
            sum += e;
        }
        float inv = 1.0f / sum;
#pragma unroll
        for (int r = 0; r < RR; r++) alpha[r] *= inv;
    }
    __syncthreads();

    float al[RR];
#pragma unroll
    for (int r = 0; r < RR; r++) al[r] = alpha[r];

    for (int f = tid; f < FOUT; f += 288) {
        float acc = RESIDUAL * __half2float(hzs[f]);
#pragma unroll
        for (int r = 0; r < RR; r++) acc += al[r] * __half2float(zs[r][f]);
        msg[(size_t)n * FOUT + f] = __float2half_rn(acc);
    }
}

// ---------------- kernel 4: multi-attention + BatchNorm ----------------
__global__ void final_kernel(const float* __restrict__ Wp1,
                             const float* __restrict__ bp1,
                             const float* __restrict__ Wp2,
                             const float* __restrict__ bp2,
                             const float* __restrict__ gamma,
                             const float* __restrict__ betaBN,
                             const float* __restrict__ mean,
                             const float* __restrict__ var,
                             float*       __restrict__ out)
{
    int n   = blockIdx.x;
    int tid = threadIdx.x;  // 128

    __shared__ float z[2][FOUT];
    __shared__ float wred[4];
    __shared__ float betasm[2];

    for (int f = tid; f < FOUT; f += 128) {
        z[0][f] = __half2float(g_msg[(size_t)n * FOUT + f]);
        z[1][f] = __half2float(g_msg[(size_t)NN * FOUT + (size_t)n * FOUT + f]);
    }
    __syncthreads();

    int i  = tid >> 6;
    int hd = tid & 63;
    float acc = 0.0f;
#pragma unroll 8
    for (int k = 0; k < FOUT; k++) acc += z[i][k] * Wp1[k * HIDD + hd];
    float t  = tanhf(acc + bp1[hd]);
    float pw = t * Wp2[hd];

#pragma unroll
    for (int off = 16; off; off >>= 1)
        pw += __shfl_down_sync(0xffffffffu, pw, off);
    if ((tid & 31) == 0) wred[tid >> 5] = pw;
    __syncthreads();
    if (tid == 0) {
        float w0 = tanhf(wred[0] + wred[1] + bp2[0]);
        float w1 = tanhf(wred[2] + wred[3] + bp2[0]);
        float m  = fmaxf(w0, w1);
        float e0 = expf(w0 - m), e1 = expf(w1 - m);
        float inv = 1.0f / (e0 + e1);
        betasm[0] = e0 * inv;
        betasm[1] = e1 * inv;
    }
    __syncthreads();

    float b0 = betasm[0], b1 = betasm[1];
    for (int f = tid; f < FOUT; f += 128) {
        float v = b0 * z[0][f] + b1 * z[1][f];
        out[(size_t)n * FOUT + f] =
            (v - mean[f]) * rsqrtf(var[f] + BN_EPS) * gamma[f] + betaBN[f];
    }
}

// ---------------- launch: single stream, 5 kernels ----------------
extern "C" void kernel_launch(void* const* d_in, const int* in_sizes, int n_in,
                              void* d_out, int out_size)
{
    const float* src_h     = (const float*)d_in[0];
    const float* src_h_img = (const float*)d_in[1];
    const int*   rel       = (const int*)  d_in[2];
    const float* h         = (const float*)d_in[3];
    const float* h_img     = (const float*)d_in[4];
    const float* W0        = (const float*)d_in[5];
    const float* a0        = (const float*)d_in[6];
    const float* W1        = (const float*)d_in[7];
    const float* a1        = (const float*)d_in[8];
    const float* Wp1       = (const float*)d_in[9];
    const float* bp1       = (const float*)d_in[10];
    const float* Wp2       = (const float*)d_in[11];
    const float* bp2       = (const float*)d_in[12];
    const float* gamma     = (const float*)d_in[13];
    const float* betaBN    = (const float*)d_in[14];
    const float* mean      = (const float*)d_in[15];
    const float* var       = (const float*)d_in[16];
    float* out = (float*)d_out;

    __half *att, *wt, *srcz, *hz, *msg;
    cudaGetSymbolAddress((void**)&att,  g_att);
    cudaGetSymbolAddress((void**)&srcz, g_srcz);
    cudaGetSymbolAddress((void**)&hz,   g_hz);
    cudaGetSymbolAddress((void**)&msg,  g_msg);
    cudaGetSymbolAddress((void**)&wt,   g_wt);

    static bool init_done = false;
    if (!init_done) {
        cudaFuncSetAttribute(gemm_tc_kernel,
                             cudaFuncAttributeMaxDynamicSharedMemorySize, GEMM_SMEM);
        init_done = true;
    }

    transposeW_kernel<<<dim3(16, 16, 2), dim3(32, 32)>>>(W0, W1, wt);
    maxpool_kernel<<<dim3(NN, 2), 128>>>(src_h, src_h_img, rel, att);
    gemm_tc_kernel<<<dim3(FOUT / 128, MBBIG + NN / 128, 2), 256, GEMM_SMEM>>>(
        att, h, h_img, wt, srcz, hz);
    gat_epilogue_kernel<<<dim3(NN, 2), 288>>>(srcz, hz, a0, a1, msg);
    final_kernel<<<NN, 128>>>(Wp1, bp1, Wp2, bp2, gamma, betaBN, mean, var, out);
}

// round 17
// speedup vs baseline: 1.1191x; 1.0186x over previous
#include <cuda_runtime.h>
#include <cuda_fp16.h>
#include <math.h>
#include <cstdint>

#define NN   16384
#define DD   16
#define FIN  512
#define FOUT 512
#define RR   8
#define HIDD 64
#define BN_EPS 1e-5f
#define RESIDUAL 0.12f

// ---------------- scratch (device globals: allocation-free), per-pass ----------------
__device__ __half g_att  [2ull * NN * RR * FIN];    // 268 MB (fp16)
__device__ __half g_srcz [2ull * NN * RR * FOUT];   // 268 MB (fp16)
__device__ __half g_hz   [2ull * NN * FOUT];        // 33 MB (fp16)
__device__ __half g_msg  [2ull * NN * FOUT];        // 33 MB (fp16)
__device__ __half g_wt   [2ull * FIN * FOUT];       // 1 MB
__device__ __half g_hconv[2ull * NN * FIN];         // 34 MB

__device__ __forceinline__ float lrelu(float x) { return x >= 0.0f ? x : 0.2f * x; }

__device__ __forceinline__ uint32_t smem_u32(const void* p) {
    uint32_t a;
    asm("{ .reg .u64 t; cvta.to.shared.u64 t, %1; cvt.u32.u64 %0, t; }" : "=r"(a) : "l"(p));
    return a;
}
__device__ __forceinline__ void cp_async16(uint32_t dst, const void* src) {
    asm volatile("cp.async.cg.shared.global [%0], [%1], 16;" :: "r"(dst), "l"(src));
}
#define CP_COMMIT() asm volatile("cp.async.commit_group;" ::: "memory")
#define CP_WAIT(n)  asm volatile("cp.async.wait_group %0;" :: "n"(n) : "memory")

__device__ __forceinline__ void ldsm_x4(uint32_t* r, uint32_t addr) {
    asm volatile("ldmatrix.sync.aligned.m8n8.x4.shared.b16 {%0,%1,%2,%3}, [%4];"
        : "=r"(r[0]), "=r"(r[1]), "=r"(r[2]), "=r"(r[3]) : "r"(addr));
}

__device__ __forceinline__ void mma_f16(float& c0, float& c1, float& c2, float& c3,
                                        uint32_t a0, uint32_t a1, uint32_t a2, uint32_t a3,
                                        uint32_t b0, uint32_t b1) {
    asm volatile(
        "mma.sync.aligned.m16n8k16.row.col.f32.f16.f16.f32 "
        "{%0,%1,%2,%3}, {%4,%5,%6,%7}, {%8,%9}, {%0,%1,%2,%3};"
        : "+f"(c0), "+f"(c1), "+f"(c2), "+f"(c3)
        : "r"(a0), "r"(a1), "r"(a2), "r"(a3), "r"(b0), "r"(b1));
}

// ---------------- kernel 0a: transpose W [K,N] -> WT [N,K], fp16 (both passes) --------
__global__ void transposeW_kernel(const float* __restrict__ W0,
                                  const float* __restrict__ W1,
                                  __half* __restrict__ WT)
{
    int pass = blockIdx.z;
    const float* W = pass ? W1 : W0;
    __half* wt = WT + (size_t)pass * FIN * FOUT;
    __shared__ float t[32][33];
    int bx = blockIdx.x * 32, by = blockIdx.y * 32;
    t[threadIdx.y][threadIdx.x] = W[(by + threadIdx.y) * FOUT + bx + threadIdx.x];
    __syncthreads();
    wt[(bx + threadIdx.y) * FIN + by + threadIdx.x] = __float2half_rn(t[threadIdx.x][threadIdx.y]);
}

// ---------------- kernel 0b: convert h to fp16 (both passes) ----------------
__global__ void convert_kernel(const float* __restrict__ h0,
                               const float* __restrict__ h1,
                               __half* __restrict__ out, int n4)
{
    int pass = blockIdx.y;
    const float* in = pass ? h1 : h0;
    __half* o = out + (size_t)pass * NN * FIN;
    int i = blockIdx.x * blockDim.x + threadIdx.x;
    if (i < n4) {
        float4 v = reinterpret_cast<const float4*>(in)[i];
        __half2 hh0 = __floats2half2_rn(v.x, v.y);
        __half2 hh1 = __floats2half2_rn(v.z, v.w);
        uint2 st;
        st.x = *reinterpret_cast<uint32_t*>(&hh0);
        st.y = *reinterpret_cast<uint32_t*>(&hh1);
        reinterpret_cast<uint2*>(o)[i] = st;
    }
}

// ---------------- kernel 1: relation maxpool, counting-sort + front-batched loads ----
__global__ void maxpool_kernel(const float* __restrict__ src0,
                               const float* __restrict__ src1,
                               const int*   __restrict__ rel,
                               __half*      __restrict__ attBase)
{
    int n    = blockIdx.x;
    int pass = blockIdx.y;
    const float* src = pass ? src1 : src0;
    __half* att = attBase + (size_t)pass * NN * RR * FIN;
    int tid = threadIdx.x;  // 128

    __shared__ int cnt[RR];
    __shared__ int ord[DD];
    __shared__ int relIdx[DD];
    __shared__ int isLast[DD];
    __shared__ int rl[DD];

    if (tid < RR) cnt[tid] = 0;
    __syncthreads();
    if (tid < DD) {
        int r = rel[n * DD + tid];
        rl[tid] = r;
        atomicAdd(&cnt[r], 1);
    }
    __syncthreads();
    if (tid == 0) {
        int pos[RR];
        int s = 0;
#pragma unroll
        for (int r = 0; r < RR; r++) { pos[r] = s; s += cnt[r]; }
#pragma unroll
        for (int d = 0; d < DD; d++) {
            int r = rl[d];
            int p = pos[r]++;
            ord[p] = d;
            relIdx[p] = r;
        }
#pragma unroll
        for (int i = 0; i < DD - 1; i++) isLast[i] = (relIdx[i + 1] != relIdx[i]);
        isLast[DD - 1] = 1;
    }
    __syncthreads();

    const float4* sp = reinterpret_cast<const float4*>(src + (size_t)n * DD * FIN);
    uint2* ap = reinterpret_cast<uint2*>(att + (size_t)n * RR * FIN);

    // zero rows for empty relations
    uint2 zz; zz.x = 0u; zz.y = 0u;
#pragma unroll
    for (int r = 0; r < RR; r++)
        if (cnt[r] == 0) ap[r * (FIN / 4) + tid] = zz;

    // front-batch all 16 row loads (MLP=16, independent LDG.128)
    float4 v[DD];
#pragma unroll
    for (int i = 0; i < DD; i++)
        v[i] = sp[ord[i] * (FIN / 4) + tid];

    const float NEG = -3.402823466e38f;
    float4 acc = make_float4(NEG, NEG, NEG, NEG);

#pragma unroll
    for (int i = 0; i < DD; i++) {
        acc.x = fmaxf(acc.x, v[i].x);
        acc.y = fmaxf(acc.y, v[i].y);
        acc.z = fmaxf(acc.z, v[i].z);
        acc.w = fmaxf(acc.w, v[i].w);
        if (isLast[i]) {
            int r = relIdx[i];
            float4 o = acc;
            if (cnt[r] != DD) {
                o.x = fmaxf(o.x, 0.0f);
                o.y = fmaxf(o.y, 0.0f);
                o.z = fmaxf(o.z, 0.0f);
                o.w = fmaxf(o.w, 0.0f);
            }
            __half2 h0 = __floats2half2_rn(o.x, o.y);
            __half2 h1 = __floats2half2_rn(o.z, o.w);
            uint2 st;
            st.x = *reinterpret_cast<uint32_t*>(&h0);
            st.y = *reinterpret_cast<uint32_t*>(&h1);
            ap[r * (FIN / 4) + tid] = st;
            acc = make_float4(NEG, NEG, NEG, NEG);
        }
    }
}

// ---------------- kernel 2: mma.sync fp16 GEMM (both passes via z) -------
// blocks y<1024: srcz = lrelu(att @ WT^T); y>=1024: hz from hconv.
// BM=128, BN=128, BK=64. 256 threads, 8 warps (2M x 4N), warp tile 64x32. 3-stage ring.
#define TSH 72
#define STAGE_HALFS ((128 + 128) * TSH)
#define GSTAGES 3
#define GEMM_SMEM (GSTAGES * STAGE_HALFS * 2)    // 110592 bytes
#define MBBIG (NN * RR / 128)

__global__ void __launch_bounds__(256, 2)
gemm_tc_kernel(const __half* __restrict__ attB,
               const __half* __restrict__ hconvB,
               const __half* __restrict__ wtB,
               __half*       __restrict__ srczB,
               __half*       __restrict__ hzB)
{
    extern __shared__ __half smh[];
    int tid  = threadIdx.x;
    int wid  = tid >> 5;
    int lane = tid & 31;
    int wm   = wid & 1;
    int wn   = wid >> 1;
    int g    = lane >> 2;
    int t    = lane & 3;
    int q    = lane >> 3;
    int lr   = lane & 7;

    int pass = blockIdx.z;
    const __half* Bt = wtB + (size_t)pass * FIN * FOUT;

    int mb = blockIdx.y;
    const __half* A;
    __half* C;
    int bm;
    if (mb < MBBIG) {
        A = attB  + (size_t)pass * NN * RR * FIN;
        C = srczB + (size_t)pass * NN * RR * FOUT;
        bm = mb * 128;
    } else {
        A = hconvB + (size_t)pass * NN * FIN;
        C = hzB    + (size_t)pass * NN * FOUT;
        bm = (mb - MBBIG) * 128;
    }
    int bn = blockIdx.x * 128;

    int row0 = tid >> 3;
    int kc0  = (tid & 7) * 8;
    const __half* Ag = A  + (size_t)(bm + row0) * FIN + kc0;
    const __half* Bg = Bt + (size_t)(bn + row0) * FIN + kc0;

    uint32_t sbase = smem_u32(smh);
    uint32_t dA = sbase + (uint32_t)(row0 * TSH + kc0) * 2;
    uint32_t dB = sbase + (uint32_t)((128 + row0) * TSH + kc0) * 2;
    const uint32_t stageB  = STAGE_HALFS * 2;
    const uint32_t rowblkB = (uint32_t)(32 * TSH) * 2;
    const size_t   rowblkG = (size_t)32 * FIN;

    uint32_t laneAoff = (uint32_t)((wm * 64 + (q & 1) * 8 + lr) * TSH + (q >> 1) * 8) * 2;
    uint32_t laneBoff = (uint32_t)((128 + wn * 32 + (q >> 1) * 8 + lr) * TSH + (q & 1) * 8) * 2;

    float acc[4][4][4];
#pragma unroll
    for (int i = 0; i < 4; i++)
#pragma unroll
        for (int j = 0; j < 4; j++)
#pragma unroll
            for (int x = 0; x < 4; x++) acc[i][j][x] = 0.0f;

    const int NK = FIN / 64;  // 8 stages

#pragma unroll
    for (int s = 0; s < GSTAGES - 1; s++) {
        int k0 = s * 64;
        uint32_t so = s * stageB;
#pragma unroll
        for (int j = 0; j < 4; j++) {
            cp_async16(dA + so + j * rowblkB, Ag + j * rowblkG + k0);
            cp_async16(dB + so + j * rowblkB, Bg + j * rowblkG + k0);
        }
        CP_COMMIT();
    }
    CP_WAIT(GSTAGES - 2);

    int buf = 0, lbuf = GSTAGES - 1;
    for (int i = 0; i < NK; i++) {
        __syncthreads();

        if (i + GSTAGES - 1 < NK) {
            int k0 = (i + GSTAGES - 1) * 64;
            uint32_t so = lbuf * stageB;
#pragma unroll
            for (int j = 0; j < 4; j++) {
                cp_async16(dA + so + j * rowblkB, Ag + j * rowblkG + k0);
                cp_async16(dB + so + j * rowblkB, Bg + j * rowblkG + k0);
            }
        }
        CP_COMMIT();

        uint32_t sa = sbase + buf * stageB;
        uint32_t aA = sa + laneAoff;
        uint32_t aB = sa + laneBoff;
#pragma unroll
        for (int kk = 0; kk < 4; kk++) {
            uint32_t a[4][4];
            uint32_t b[2][4];
#pragma unroll
            for (int mt = 0; mt < 4; mt++)
                ldsm_x4(a[mt], aA + (uint32_t)(mt * 16 * TSH + kk * 16) * 2);
#pragma unroll
            for (int n2 = 0; n2 < 2; n2++)
                ldsm_x4(b[n2], aB + (uint32_t)(n2 * 16 * TSH + kk * 16) * 2);
#pragma unroll
            for (int mt = 0; mt < 4; mt++)
#pragma unroll
                for (int nt = 0; nt < 4; nt++)
                    mma_f16(acc[mt][nt][0], acc[mt][nt][1], acc[mt][nt][2], acc[mt][nt][3],
                            a[mt][0], a[mt][1], a[mt][2], a[mt][3],
                            b[nt >> 1][(nt & 1) * 2], b[nt >> 1][(nt & 1) * 2 + 1]);
        }

        CP_WAIT(GSTAGES - 2);
        buf  = (buf  == GSTAGES - 1) ? 0 : buf + 1;
        lbuf = (lbuf == GSTAGES - 1) ? 0 : lbuf + 1;
    }

    // ---- epilogue: lrelu + fp16 store ----
#pragma unroll
    for (int mt = 0; mt < 4; mt++) {
        int mrow = bm + wm * 64 + mt * 16 + g;
#pragma unroll
        for (int nt = 0; nt < 4; nt++) {
            int ncol = bn + wn * 32 + nt * 8 + t * 2;
            __half2 lo = __floats2half2_rn(lrelu(acc[mt][nt][0]), lrelu(acc[mt][nt][1]));
            __half2 hi = __floats2half2_rn(lrelu(acc[mt][nt][2]), lrelu(acc[mt][nt][3]));
            *reinterpret_cast<__half2*>(C + (size_t)mrow * FOUT + ncol)       = lo;
            *reinterpret_cast<__half2*>(C + (size_t)(mrow + 8) * FOUT + ncol) = hi;
        }
    }
}

// ---------------- kernel 3: GAT softmax epilogue (fp16 in/out, both passes) ----------
__global__ void gat_epilogue_kernel(const __half* __restrict__ srczB,
                                    const __half* __restrict__ hzB,
                                    const float*  __restrict__ a0p,
                                    const float*  __restrict__ a1p,
                                    __half*       __restrict__ msgB)
{
    int n    = blockIdx.x;
    int pass = blockIdx.y;
    const __half* srcz = srczB + (size_t)pass * NN * RR * FOUT;
    const __half* hz   = hzB   + (size_t)pass * NN * FOUT;
    const float* a_attn = pass ? a1p : a0p;
    __half* msg = msgB + (size_t)pass * NN * FOUT;

    int tid = threadIdx.x;  // 288 = 9 warps
    int warp = tid >> 5, lane = tid & 31;

    __shared__ __half zs[RR][FOUT];
    __shared__ __half hzs[FOUT];
    __shared__ float scoresm[9];
    __shared__ float alpha[RR];

    const uint4* zp = reinterpret_cast<const uint4*>(srcz + (size_t)n * RR * FOUT);
    uint4* zsm = reinterpret_cast<uint4*>(&zs[0][0]);
    for (int i = tid; i < RR * FOUT / 8; i += 288) zsm[i] = zp[i];
    const uint4* hp = reinterpret_cast<const uint4*>(hz + (size_t)n * FOUT);
    uint4* hsm = reinterpret_cast<uint4*>(hzs);
    for (int i = tid; i < FOUT / 8; i += 288) hsm[i] = hp[i];
    __syncthreads();

    {
        const __half* src = (warp < 8) ? &zs[warp][0] : hzs;
        const float* av = a_attn + (warp < 8 ? 0 : FOUT);
        float s = 0.0f;
#pragma unroll
        for (int c = 0; c < 2; c++) {
            int base = (lane + c * 32) * 8;
            uint4 hv = *reinterpret_cast<const uint4*>(src + base);
            const __half2* hp2 = reinterpret_cast<const __half2*>(&hv);
            const float4* a4 = reinterpret_cast<const float4*>(av + base);
            float4 aa0 = a4[0], aa1 = a4[1];
            float2 z0 = __half22float2(hp2[0]);
            float2 z1 = __half22float2(hp2[1]);
            float2 z2 = __half22float2(hp2[2]);
            float2 z3 = __half22float2(hp2[3]);
            s += z0.x * aa0.x + z0.y * aa0.y + z1.x * aa0.z + z1.y * aa0.w;
            s += z2.x * aa1.x + z2.y * aa1.y + z3.x * aa1.z + z3.y * aa1.w;
        }
#pragma unroll
        for (int off = 16; off; off >>= 1)
            s += __shfl_down_sync(0xffffffffu, s, off);
        if (lane == 0) scoresm[warp] = s;
    }
    __syncthreads();

    if (tid == 0) {
        float sh = scoresm[8];
        float sc[RR], mx = -3.402823466e38f;
#pragma unroll
        for (int r = 0; r < RR; r++) {
            sc[r] = lrelu(scoresm[r] + sh);
            mx = fmaxf(mx, sc[r]);
        }
        float sum = 0.0f;
#pragma unroll
        for (int r = 0; r < RR; r++) {
            float e = expf(sc[r] - mx);
            alpha[r] = e;
            sum += e;
        }
        float inv = 1.0f / sum;
#pragma unroll
        for (int r = 0; r < RR; r++) alpha[r] *= inv;
    }
    __syncthreads();

    float al[RR];
#pragma unroll
    for (int r = 0; r < RR; r++) al[r] = alpha[r];

    for (int f = tid; f < FOUT; f += 288) {
        float acc = RESIDUAL * __half2float(hzs[f]);
#pragma unroll
        for (int r = 0; r < RR; r++) acc += al[r] * __half2float(zs[r][f]);
        msg[(size_t)n * FOUT + f] = __float2half_rn(acc);
    }
}

// ---------------- kernel 4: multi-attention + BatchNorm ----------------
__global__ void final_kernel(const float* __restrict__ Wp1,
                             const float* __restrict__ bp1,
                             const float* __restrict__ Wp2,
                             const float* __restrict__ bp2,
                             const float* __restrict__ gamma,
                             const float* __restrict__ betaBN,
                             const float* __restrict__ mean,
                             const float* __restrict__ var,
                             float*       __restrict__ out)
{
    int n   = blockIdx.x;
    int tid = threadIdx.x;  // 128

    __shared__ float z[2][FOUT];
    __shared__ float wred[4];
    __shared__ float betasm[2];

    for (int f = tid; f < FOUT; f += 128) {
        z[0][f] = __half2float(g_msg[(size_t)n * FOUT + f]);
        z[1][f] = __half2float(g_msg[(size_t)NN * FOUT + (size_t)n * FOUT + f]);
    }
    __syncthreads();

    int i  = tid >> 6;
    int hd = tid & 63;
    float acc = 0.0f;
#pragma unroll 8
    for (int k = 0; k < FOUT; k++) acc += z[i][k] * Wp1[k * HIDD + hd];
    float t  = tanhf(acc + bp1[hd]);
    float pw = t * Wp2[hd];

#pragma unroll
    for (int off = 16; off; off >>= 1)
        pw += __shfl_down_sync(0xffffffffu, pw, off);
    if ((tid & 31) == 0) wred[tid >> 5] = pw;
    __syncthreads();
    if (tid == 0) {
        float w0 = tanhf(wred[0] + wred[1] + bp2[0]);
        float w1 = tanhf(wred[2] + wred[3] + bp2[0]);
        float m  = fmaxf(w0, w1);
        float e0 = expf(w0 - m), e1 = expf(w1 - m);
        float inv = 1.0f / (e0 + e1);
        betasm[0] = e0 * inv;
        betasm[1] = e1 * inv;
    }
    __syncthreads();

    float b0 = betasm[0], b1 = betasm[1];
    for (int f = tid; f < FOUT; f += 128) {
        float v = b0 * z[0][f] + b1 * z[1][f];
        out[(size_t)n * FOUT + f] =
            (v - mean[f]) * rsqrtf(var[f] + BN_EPS) * gamma[f] + betaBN[f];
    }
}

// ---------------- launch: single stream, 6 kernels ----------------
extern "C" void kernel_launch(void* const* d_in, const int* in_sizes, int n_in,
                              void* d_out, int out_size)
{
    const float* src_h     = (const float*)d_in[0];
    const float* src_h_img = (const float*)d_in[1];
    const int*   rel       = (const int*)  d_in[2];
    const float* h         = (const float*)d_in[3];
    const float* h_img     = (const float*)d_in[4];
    const float* W0        = (const float*)d_in[5];
    const float* a0        = (const float*)d_in[6];
    const float* W1        = (const float*)d_in[7];
    const float* a1        = (const float*)d_in[8];
    const float* Wp1       = (const float*)d_in[9];
    const float* bp1       = (const float*)d_in[10];
    const float* Wp2       = (const float*)d_in[11];
    const float* bp2       = (const float*)d_in[12];
    const float* gamma     = (const float*)d_in[13];
    const float* betaBN    = (const float*)d_in[14];
    const float* mean      = (const float*)d_in[15];
    const float* var       = (const float*)d_in[16];
    float* out = (float*)d_out;

    __half *att, *wt, *srcz, *hz, *msg, *hconv;
    cudaGetSymbolAddress((void**)&att,   g_att);
    cudaGetSymbolAddress((void**)&srcz,  g_srcz);
    cudaGetSymbolAddress((void**)&hz,    g_hz);
    cudaGetSymbolAddress((void**)&msg,   g_msg);
    cudaGetSymbolAddress((void**)&wt,    g_wt);
    cudaGetSymbolAddress((void**)&hconv, g_hconv);

    static bool init_done = false;
    if (!init_done) {
        cudaFuncSetAttribute(gemm_tc_kernel,
                             cudaFuncAttributeMaxDynamicSharedMemorySize, GEMM_SMEM);
        init_done = true;
    }

    transposeW_kernel<<<dim3(16, 16, 2), dim3(32, 32)>>>(W0, W1, wt);
    convert_kernel<<<dim3((NN * FIN / 4 + 255) / 256, 2), 256>>>(h, h_img, hconv, NN * FIN / 4);
    maxpool_kernel<<<dim3(NN, 2), 128>>>(src_h, src_h_img, rel, att);
    gemm_tc_kernel<<<dim3(FOUT / 128, MBBIG + NN / 128, 2), 256, GEMM_SMEM>>>(
        att, hconv, wt, srcz, hz);
    gat_epilogue_kernel<<<dim3(NN, 2), 288>>>(srcz, hz, a0, a1, msg);
    final_kernel<<<NN, 128>>>(Wp1, bp1, Wp2, bp2, gamma, betaBN, mean, var, out);
}